// round 11
// baseline (speedup 1.0000x reference)
#include <cuda_runtime.h>
#include <math.h>
#include <stdint.h>

// ---------------------------------------------------------------------------
// MultilayerGRU  B=64 S=1024 I=128 H=512 L=3 O=128
// Persistent cooperative kernel: 128 CTAs (1/SM), all weights SMEM-resident,
// 6 grid barriers per timestep (z/r phase + g/combine phase per layer).
// ---------------------------------------------------------------------------

#define NCTA 128
#define NTHR 256
#define Bx   64
#define Sx   1024
#define Ix   128
#define Hx   512
#define Lx   3
#define Ox   128
#define CPT  4          // columns per CTA per gate (512/128)
#define HQ   (Hx/4)     // 128 float4 per row
#define IQ   (Ix/4)     // 32

// ---- shared memory layout (float offsets) ----
#define WHZ0 0
#define WHR0 2048
#define WHG0 4096
#define WX0Z 6144
#define WX0R 6656
#define WX0G 7168
#define WXZ1 7680
#define WXR1 9728
#define WXG1 11776
#define WHZ1 13824
#define WHR1 15872
#define WHG1 17920
#define WXZ2 19968
#define WXR2 22016
#define WXG2 24064
#define WHZ2 26112
#define WHR2 28160
#define WHG2 30208
#define WYOF 32256
#define SM_Z  32768
#define SM_XG 33024
#define SM_Y  33280
#define SM_BZ 33536
#define SM_BR 33552
#define SM_BG 33568
#define SM_BY 33584
#define SMEM_FLOATS 33600
#define SMEM_BYTES  (SMEM_FLOATS * 4)

// ---- global scratch (static allocations; no runtime alloc) ----
// layer-0 input transposed & float4-blocked: [s][j4][b] (each elem = x[b][s][4j..4j+3])
__device__ float4 g_x0t[(size_t)Sx * IQ * Bx];
// hidden state, blocked: [l][k4][b]
__device__ float4 g_h[Lx * HQ * Bx];
// r*h broadcast buffer, blocked: [k4][b]
__device__ float4 g_rh[HQ * Bx];
__device__ unsigned g_bar;

// ---------------------------------------------------------------------------
__device__ __forceinline__ float dot4(float4 a, float4 b, float acc) {
    acc = fmaf(a.x, b.x, acc);
    acc = fmaf(a.y, b.y, acc);
    acc = fmaf(a.z, b.z, acc);
    acc = fmaf(a.w, b.w, acc);
    return acc;
}

__device__ __forceinline__ void gbar(unsigned target) {
    __syncthreads();
    if (threadIdx.x == 0) {
        unsigned* p = &g_bar;
        asm volatile("red.release.gpu.global.add.u32 [%0], 1;" :: "l"(p) : "memory");
        unsigned v;
        do {
            asm volatile("ld.acquire.gpu.global.u32 %0, [%1];" : "=r"(v) : "l"(p) : "memory");
        } while (v < target);
    }
    __syncthreads();
}

// Phase 1 of layer l: z = sigm(h Whz^T + x Wxz^T + bz), r likewise,
// xg = x Wxg^T + bg (kept in smem), rh = r*h written to global.
__device__ __forceinline__ void phase1(
    float* sw, int b, int cp, int cta,
    const float4* __restrict__ hsrc,   // g_h + l*HQ*Bx
    const float4* __restrict__ xsrc,   // blocked [j4][b]
    int xq,                            // IQ (layer 0) or HQ (layers 1,2)
    int whz, int whr, int wxz, int wxr, int wxg, int l)
{
    const float4* wzp = (const float4*)(sw + whz + cp * Hx);
    const float4* wrp = (const float4*)(sw + whr + cp * Hx);
    float az = 0.f, ar = 0.f;
#pragma unroll 4
    for (int k4 = 0; k4 < HQ; k4++) {
        float4 hv = hsrc[k4 * Bx + b];
        az = dot4(hv, wzp[k4], az);
        ar = dot4(hv, wrp[k4], ar);
    }
    const float4* xzp = (const float4*)(sw + wxz + cp * (xq * 4));
    const float4* xrp = (const float4*)(sw + wxr + cp * (xq * 4));
    const float4* xgp = (const float4*)(sw + wxg + cp * (xq * 4));
    float ag = 0.f;
#pragma unroll 4
    for (int j4 = 0; j4 < xq; j4++) {
        float4 xv = xsrc[j4 * Bx + b];
        az = dot4(xv, xzp[j4], az);
        ar = dot4(xv, xrp[j4], ar);
        ag = dot4(xv, xgp[j4], ag);
    }
    float z = 1.f / (1.f + expf(-(az + sw[SM_BZ + l * 4 + cp])));
    float r = 1.f / (1.f + expf(-(ar + sw[SM_BR + l * 4 + cp])));
    sw[SM_Z  + cp * 64 + b] = z;
    sw[SM_XG + cp * 64 + b] = ag + sw[SM_BG + l * 4 + cp];
    float hcur = ((const float*)hsrc)[(cta * Bx + b) * 4 + cp];
    ((float*)g_rh)[(cta * Bx + b) * 4 + cp] = r * hcur;
}

// Phase 2 of layer l: g = tanh((r*h) Whg^T + xg), h_new = g + z*(h - g).
__device__ __forceinline__ void phase2(float* sw, int b, int cp, int cta, int l, int whg)
{
    const float4* wgp  = (const float4*)(sw + whg + cp * Hx);
    const float4* rsrc = g_rh;
    float ag = sw[SM_XG + cp * 64 + b];
#pragma unroll 4
    for (int k4 = 0; k4 < HQ; k4++)
        ag = dot4(rsrc[k4 * Bx + b], wgp[k4], ag);
    float g = tanhf(ag);
    float z = sw[SM_Z + cp * 64 + b];
    float* hp = ((float*)g_h) + (((size_t)l * HQ + cta) * Bx + b) * 4 + cp;
    float hold = *hp;
    *hp = fmaf(z, hold - g, g);
}

// Output projection y[tdst] = h2 @ Wy^T + by  (K split 4-ways over cp).
__device__ __forceinline__ void ycompute(float* sw, int b, int cp, int cta,
                                         float* __restrict__ out, int tdst)
{
    const float4* h2  = g_h + 2 * HQ * Bx;
    const float4* wyp = (const float4*)(sw + WYOF);
    float ay = 0.f;
    int k0 = cp * 32;
#pragma unroll 8
    for (int k4 = k0; k4 < k0 + 32; k4++)
        ay = dot4(h2[k4 * Bx + b], wyp[k4], ay);
    sw[SM_Y + cp * 64 + b] = ay;
    __syncthreads();
    if (cp == 0) {
        float y = sw[SM_Y + b] + sw[SM_Y + 64 + b] + sw[SM_Y + 128 + b] +
                  sw[SM_Y + 192 + b] + sw[SM_BY];
        out[((size_t)b * Sx + tdst) * Ox + cta] = y;
    }
}

// ---------------------------------------------------------------------------
__global__ void init_kernel(const float* __restrict__ in, const float* __restrict__ hs)
{
    size_t i = (size_t)blockIdx.x * blockDim.x + threadIdx.x;
    size_t stride = (size_t)gridDim.x * blockDim.x;
    if (i == 0) g_bar = 0;

    // hidden state: hs is (B, L, H)
    for (size_t idx = i; idx < (size_t)Bx * Lx * Hx; idx += stride) {
        int b = (int)(idx / (Lx * Hx));
        int l = (int)((idx / Hx) % Lx);
        int k = (int)(idx % Hx);
        ((float*)g_h)[(((size_t)l * HQ + (k >> 2)) * Bx + b) * 4 + (k & 3)] = hs[idx];
    }
    // input: (B, S, I) -> blocked [s][j4][b][4]
    for (size_t idx = i; idx < (size_t)Bx * Sx * Ix; idx += stride) {
        int b = (int)(idx / ((size_t)Sx * Ix));
        int s = (int)((idx / Ix) % Sx);
        int j = (int)(idx % Ix);
        ((float*)g_x0t)[(((size_t)s * IQ + (j >> 2)) * Bx + b) * 4 + (j & 3)] = in[idx];
    }
}

__global__ void __launch_bounds__(NTHR, 1) gru_main(
    const float* __restrict__ Wx0z, const float* __restrict__ Wx0r, const float* __restrict__ Wx0g,
    const float* __restrict__ Wxz,  const float* __restrict__ Wxr,  const float* __restrict__ Wxg,
    const float* __restrict__ Whz,  const float* __restrict__ Whr,  const float* __restrict__ Whg,
    const float* __restrict__ bz,   const float* __restrict__ br,   const float* __restrict__ bg,
    const float* __restrict__ Wy,   const float* __restrict__ by,
    float* __restrict__ out)
{
    extern __shared__ float sw[];
    const int tid = threadIdx.x;
    const int cta = blockIdx.x;
    const int nb  = cta * CPT;

    // ---- load this CTA's weight slices into SMEM (once) ----
    for (int i = tid; i < CPT * Hx; i += NTHR) {
        int cp = i >> 9, k = i & 511;
        int row = nb + cp;
        sw[WHZ0 + i] = Whz[((size_t)(0 * Hx + row)) * Hx + k];
        sw[WHR0 + i] = Whr[((size_t)(0 * Hx + row)) * Hx + k];
        sw[WHG0 + i] = Whg[((size_t)(0 * Hx + row)) * Hx + k];
        sw[WHZ1 + i] = Whz[((size_t)(1 * Hx + row)) * Hx + k];
        sw[WHR1 + i] = Whr[((size_t)(1 * Hx + row)) * Hx + k];
        sw[WHG1 + i] = Whg[((size_t)(1 * Hx + row)) * Hx + k];
        sw[WHZ2 + i] = Whz[((size_t)(2 * Hx + row)) * Hx + k];
        sw[WHR2 + i] = Whr[((size_t)(2 * Hx + row)) * Hx + k];
        sw[WHG2 + i] = Whg[((size_t)(2 * Hx + row)) * Hx + k];
        sw[WXZ1 + i] = Wxz[((size_t)(0 * Hx + row)) * Hx + k];
        sw[WXR1 + i] = Wxr[((size_t)(0 * Hx + row)) * Hx + k];
        sw[WXG1 + i] = Wxg[((size_t)(0 * Hx + row)) * Hx + k];
        sw[WXZ2 + i] = Wxz[((size_t)(1 * Hx + row)) * Hx + k];
        sw[WXR2 + i] = Wxr[((size_t)(1 * Hx + row)) * Hx + k];
        sw[WXG2 + i] = Wxg[((size_t)(1 * Hx + row)) * Hx + k];
    }
    for (int i = tid; i < CPT * Ix; i += NTHR) {
        int cp = i >> 7, j = i & 127;
        int row = nb + cp;
        sw[WX0Z + i] = Wx0z[(size_t)row * Ix + j];
        sw[WX0R + i] = Wx0r[(size_t)row * Ix + j];
        sw[WX0G + i] = Wx0g[(size_t)row * Ix + j];
    }
    for (int i = tid; i < Hx; i += NTHR)
        sw[WYOF + i] = Wy[(size_t)cta * Hx + i];
    if (tid < 12) {
        int l = tid >> 2, cp = tid & 3;
        sw[SM_BZ + tid] = bz[l * Hx + nb + cp];
        sw[SM_BR + tid] = br[l * Hx + nb + cp];
        sw[SM_BG + tid] = bg[l * Hx + nb + cp];
    }
    if (tid == 0) sw[SM_BY] = by[cta];
    __syncthreads();

    const int b  = tid & 63;
    const int cp = tid >> 6;
    const float4* h0 = g_h;
    const float4* h1 = g_h + 1 * HQ * Bx;
    const float4* h2 = g_h + 2 * HQ * Bx;

    unsigned bv = 0;
    for (int t = 0; t < Sx; t++) {
        // P(0,1): layer-0 z/r/xg  (+ y for step t-1, h2 still holds step t-1)
        phase1(sw, b, cp, cta, h0, g_x0t + (size_t)t * IQ * Bx, IQ,
               WHZ0, WHR0, WX0Z, WX0R, WX0G, 0);
        if (t > 0) ycompute(sw, b, cp, cta, out, t - 1);
        bv++; gbar(bv * NCTA);
        // P(0,2)
        phase2(sw, b, cp, cta, 0, WHG0);
        bv++; gbar(bv * NCTA);
        // P(1,1): x = new h0
        phase1(sw, b, cp, cta, h1, h0, HQ, WHZ1, WHR1, WXZ1, WXR1, WXG1, 1);
        bv++; gbar(bv * NCTA);
        // P(1,2)
        phase2(sw, b, cp, cta, 1, WHG1);
        bv++; gbar(bv * NCTA);
        // P(2,1): x = new h1
        phase1(sw, b, cp, cta, h2, h1, HQ, WHZ2, WHR2, WXZ2, WXR2, WXG2, 2);
        bv++; gbar(bv * NCTA);
        // P(2,2)
        phase2(sw, b, cp, cta, 2, WHG2);
        bv++; gbar(bv * NCTA);
    }
    // y for the final timestep
    ycompute(sw, b, cp, cta, out, Sx - 1);

    // hidden_out (B, L, H)
    for (int l = 0; l < Lx; l++) {
        float hv = ((const float*)g_h)[(((size_t)l * HQ + cta) * Bx + b) * 4 + cp];
        out[(size_t)Bx * Sx * Ox + ((size_t)b * Lx + l) * Hx + nb + cp] = hv;
    }
}

// ---------------------------------------------------------------------------
extern "C" void kernel_launch(void* const* d_in, const int* in_sizes, int n_in,
                              void* d_out, int out_size)
{
    const float* input = (const float*)d_in[0];
    const float* hs    = (const float*)d_in[1];
    const float* Wx0z  = (const float*)d_in[2];
    const float* Wx0r  = (const float*)d_in[3];
    const float* Wx0g  = (const float*)d_in[4];
    const float* Wxz   = (const float*)d_in[5];
    const float* Wxr   = (const float*)d_in[6];
    const float* Wxg   = (const float*)d_in[7];
    const float* Whz   = (const float*)d_in[8];
    const float* Whr   = (const float*)d_in[9];
    const float* Whg   = (const float*)d_in[10];
    const float* bz    = (const float*)d_in[11];
    const float* br    = (const float*)d_in[12];
    const float* bg    = (const float*)d_in[13];
    const float* Wy    = (const float*)d_in[14];
    const float* by    = (const float*)d_in[15];
    float* out = (float*)d_out;

    cudaFuncSetAttribute(gru_main, cudaFuncAttributeMaxDynamicSharedMemorySize, SMEM_BYTES);

    init_kernel<<<1024, 256>>>(input, hs);
    gru_main<<<NCTA, NTHR, SMEM_BYTES>>>(Wx0z, Wx0r, Wx0g, Wxz, Wxr, Wxg,
                                         Whz, Whr, Whg, bz, br, bg, Wy, by, out);
}

// round 12
// speedup vs baseline: 2.3233x; 2.3233x over previous
#include <cuda_runtime.h>
#include <math.h>
#include <stdint.h>

// ---------------------------------------------------------------------------
// MultilayerGRU  B=64 S=1024 I=128 H=512 L=3 O=128
// Persistent cooperative kernel, 128 CTAs x 512 threads.
// Thread (q=tid>>6, b=tid&63) computes K-partial dots for ALL 4 of this CTA's
// output columns over k-slice q (1/8 of K), packed fp32x2 FMAs, SMEM reduce.
// 6 grid barriers per timestep.
// ---------------------------------------------------------------------------

#define NCTA 128
#define NTHR 512
#define Bx   64
#define Sx   1024
#define Ix   128
#define Hx   512
#define Lx   3
#define Ox   128
#define CPT  4          // output columns per CTA per gate
#define HQ   (Hx/4)     // 128 float4 per activation row
#define IQ   (Ix/4)     // 32

// ---- shared memory layout (float offsets) ----
#define WHZ0 0
#define WHR0 2048
#define WHG0 4096
#define WX0Z 6144
#define WX0R 6656
#define WX0G 7168
#define WXZ1 7680
#define WXR1 9728
#define WXG1 11776
#define WHZ1 13824
#define WHR1 15872
#define WHG1 17920
#define WXZ2 19968
#define WXR2 22016
#define WXG2 24064
#define WHZ2 26112
#define WHR2 28160
#define WHG2 30208
#define WYOF 32256
#define SM_RED 32768            // 8 q * 16 slots * 64 b = 8192 floats
#define SM_BZ  40960
#define SM_BR  40976
#define SM_BG  40992
#define SM_BY  41008
#define SMEM_FLOATS 41024
#define SMEM_BYTES  (SMEM_FLOATS * 4)

// ---- global scratch ----
__device__ float4 g_x0t[(size_t)Sx * IQ * Bx];   // [s][j4][b]
__device__ float4 g_h[Lx * HQ * Bx];             // [l][k4][b]
__device__ float4 g_rh[HQ * Bx];                 // [k4][b]
__device__ unsigned g_bar;

// ---------------------------------------------------------------------------
__device__ __forceinline__ unsigned long long pfma(unsigned long long a,
                                                   unsigned long long b,
                                                   unsigned long long c) {
    unsigned long long d;
    asm("fma.rn.f32x2 %0, %1, %2, %3;" : "=l"(d) : "l"(a), "l"(b), "l"(c));
    return d;
}

__device__ __forceinline__ float phsum(unsigned long long v) {
    float lo = __uint_as_float((unsigned)(v & 0xffffffffULL));
    float hi = __uint_as_float((unsigned)(v >> 32));
    return lo + hi;
}

__device__ __forceinline__ float fsigm(float x) {
    return __fdividef(1.f, 1.f + __expf(-x));
}
__device__ __forceinline__ float ftanh(float x) {
    float e = __expf(-2.f * x);
    return __fdividef(1.f - e, 1.f + e);
}

__device__ __forceinline__ void gbar(unsigned target) {
    __syncthreads();
    if (threadIdx.x == 0) {
        unsigned* p = &g_bar;
        asm volatile("red.release.gpu.global.add.u32 [%0], 1;" :: "l"(p) : "memory");
        unsigned v;
        do {
            asm volatile("ld.acquire.gpu.global.u32 %0, [%1];" : "=r"(v) : "l"(p) : "memory");
        } while (v < target);
    }
    __syncthreads();
}

// ---------------------------------------------------------------------------
// Phase-1 partials: z/r over h, z/r/g over x, for all 4 columns, k-slice q.
template<int XKPT, int XSTR>
__device__ __forceinline__ void p1_partials(
    float* sw, int b, int q,
    const ulonglong2* __restrict__ hsrc,
    const ulonglong2* __restrict__ xsrc,
    int whz, int whr, int wxz, int wxr, int wxg)
{
    const ulonglong2* wz2 = (const ulonglong2*)(sw + whz);
    const ulonglong2* wr2 = (const ulonglong2*)(sw + whr);
    const ulonglong2* xz2 = (const ulonglong2*)(sw + wxz);
    const ulonglong2* xr2 = (const ulonglong2*)(sw + wxr);
    const ulonglong2* xg2 = (const ulonglong2*)(sw + wxg);

    unsigned long long az[4], ar[4], ag[4];
#pragma unroll
    for (int cp = 0; cp < 4; cp++) { az[cp] = 0ULL; ar[cp] = 0ULL; ag[cp] = 0ULL; }

    const int k0 = q * 16;
#pragma unroll 4
    for (int k4 = k0; k4 < k0 + 16; k4++) {
        ulonglong2 hv = hsrc[k4 * Bx + b];
#pragma unroll
        for (int cp = 0; cp < 4; cp++) {
            ulonglong2 w1 = wz2[cp * 128 + k4];
            ulonglong2 w2 = wr2[cp * 128 + k4];
            az[cp] = pfma(hv.x, w1.x, az[cp]);
            ar[cp] = pfma(hv.x, w2.x, ar[cp]);
            az[cp] = pfma(hv.y, w1.y, az[cp]);
            ar[cp] = pfma(hv.y, w2.y, ar[cp]);
        }
    }

    const int j0 = q * XKPT;
#pragma unroll 2
    for (int j4 = j0; j4 < j0 + XKPT; j4++) {
        ulonglong2 xv = xsrc[j4 * Bx + b];
#pragma unroll
        for (int cp = 0; cp < 4; cp++) {
            ulonglong2 w1 = xz2[cp * XSTR + j4];
            ulonglong2 w2 = xr2[cp * XSTR + j4];
            ulonglong2 w3 = xg2[cp * XSTR + j4];
            az[cp] = pfma(xv.x, w1.x, az[cp]);
            ar[cp] = pfma(xv.x, w2.x, ar[cp]);
            ag[cp] = pfma(xv.x, w3.x, ag[cp]);
            az[cp] = pfma(xv.y, w1.y, az[cp]);
            ar[cp] = pfma(xv.y, w2.y, ar[cp]);
            ag[cp] = pfma(xv.y, w3.y, ag[cp]);
        }
    }

#pragma unroll
    for (int cp = 0; cp < 4; cp++) {
        sw[SM_RED + (q * 16 + cp)     * Bx + b] = phsum(az[cp]);
        sw[SM_RED + (q * 16 + 4 + cp) * Bx + b] = phsum(ar[cp]);
        sw[SM_RED + (q * 16 + 8 + cp) * Bx + b] = phsum(ag[cp]);
    }
}

// Phase-1 finalize (after __syncthreads): threads q<4 own column c=q.
__device__ __forceinline__ void p1_final(
    float* sw, int b, int q, int cta, int l,
    const float* __restrict__ hbase,
    float& z_reg, float& xg_reg)
{
    if (q >= 4) return;
    const int c = q;
    float sz = 0.f, sr = 0.f, sg = 0.f;
#pragma unroll
    for (int qq = 0; qq < 8; qq++) {
        sz += sw[SM_RED + (qq * 16 + c)     * Bx + b];
        sr += sw[SM_RED + (qq * 16 + 4 + c) * Bx + b];
        sg += sw[SM_RED + (qq * 16 + 8 + c) * Bx + b];
    }
    float z = fsigm(sz + sw[SM_BZ + l * 4 + c]);
    float r = fsigm(sr + sw[SM_BR + l * 4 + c]);
    z_reg  = z;
    xg_reg = sg + sw[SM_BG + l * 4 + c];
    float hcur = hbase[(cta * Bx + b) * 4 + c];
    ((float*)g_rh)[(cta * Bx + b) * 4 + c] = r * hcur;
}

// Phase-2 partials: g-dot over rh for all 4 columns, k-slice q.
__device__ __forceinline__ void p2_partials(float* sw, int b, int q, int whg)
{
    const ulonglong2* wg2 = (const ulonglong2*)(sw + whg);
    const ulonglong2* rh2 = (const ulonglong2*)g_rh;
    unsigned long long a[4] = {0ULL, 0ULL, 0ULL, 0ULL};
    const int k0 = q * 16;
#pragma unroll 4
    for (int k4 = k0; k4 < k0 + 16; k4++) {
        ulonglong2 rv = rh2[k4 * Bx + b];
#pragma unroll
        for (int cp = 0; cp < 4; cp++) {
            ulonglong2 w = wg2[cp * 128 + k4];
            a[cp] = pfma(rv.x, w.x, a[cp]);
            a[cp] = pfma(rv.y, w.y, a[cp]);
        }
    }
#pragma unroll
    for (int cp = 0; cp < 4; cp++)
        sw[SM_RED + (q * 16 + cp) * Bx + b] = phsum(a[cp]);
}

__device__ __forceinline__ void p2_final(
    float* sw, int b, int q, int cta, int l, float z_reg, float xg_reg)
{
    if (q >= 4) return;
    const int c = q;
    float s = 0.f;
#pragma unroll
    for (int qq = 0; qq < 8; qq++)
        s += sw[SM_RED + (qq * 16 + c) * Bx + b];
    float g = ftanh(s + xg_reg);
    float* hp = ((float*)g_h) + (((size_t)l * HQ + cta) * Bx + b) * 4 + c;
    float hold = *hp;
    *hp = fmaf(z_reg, hold - g, g);
}

// Output-projection partial over h2 (folded into P01 of step t+1).
__device__ __forceinline__ void y_partial(float* sw, int b, int q)
{
    const ulonglong2* h2  = (const ulonglong2*)(g_h + 2 * HQ * Bx);
    const ulonglong2* wy2 = (const ulonglong2*)(sw + WYOF);
    unsigned long long ay = 0ULL;
    const int k0 = q * 16;
#pragma unroll 4
    for (int k4 = k0; k4 < k0 + 16; k4++) {
        ulonglong2 hv = h2[k4 * Bx + b];
        ulonglong2 w  = wy2[k4];
        ay = pfma(hv.x, w.x, ay);
        ay = pfma(hv.y, w.y, ay);
    }
    sw[SM_RED + (q * 16 + 12) * Bx + b] = phsum(ay);
}

__device__ __forceinline__ void y_final(float* sw, int b, int cta,
                                        float* __restrict__ out, int tdst)
{
    float s = 0.f;
#pragma unroll
    for (int qq = 0; qq < 8; qq++)
        s += sw[SM_RED + (qq * 16 + 12) * Bx + b];
    out[((size_t)b * Sx + tdst) * Ox + cta] = s + sw[SM_BY];
}

// ---------------------------------------------------------------------------
__global__ void init_kernel(const float* __restrict__ in, const float* __restrict__ hs)
{
    size_t i = (size_t)blockIdx.x * blockDim.x + threadIdx.x;
    size_t stride = (size_t)gridDim.x * blockDim.x;
    if (i == 0) g_bar = 0;

    for (size_t idx = i; idx < (size_t)Bx * Lx * Hx; idx += stride) {
        int b = (int)(idx / (Lx * Hx));
        int l = (int)((idx / Hx) % Lx);
        int k = (int)(idx % Hx);
        ((float*)g_h)[(((size_t)l * HQ + (k >> 2)) * Bx + b) * 4 + (k & 3)] = hs[idx];
    }
    for (size_t idx = i; idx < (size_t)Bx * Sx * Ix; idx += stride) {
        int b = (int)(idx / ((size_t)Sx * Ix));
        int s = (int)((idx / Ix) % Sx);
        int j = (int)(idx % Ix);
        ((float*)g_x0t)[(((size_t)s * IQ + (j >> 2)) * Bx + b) * 4 + (j & 3)] = in[idx];
    }
}

__global__ void __launch_bounds__(NTHR, 1) gru_main(
    const float* __restrict__ Wx0z, const float* __restrict__ Wx0r, const float* __restrict__ Wx0g,
    const float* __restrict__ Wxz,  const float* __restrict__ Wxr,  const float* __restrict__ Wxg,
    const float* __restrict__ Whz,  const float* __restrict__ Whr,  const float* __restrict__ Whg,
    const float* __restrict__ bz,   const float* __restrict__ br,   const float* __restrict__ bg,
    const float* __restrict__ Wy,   const float* __restrict__ by,
    float* __restrict__ out)
{
    extern __shared__ float sw[];
    const int tid = threadIdx.x;
    const int cta = blockIdx.x;
    const int nb  = cta * CPT;

    // ---- load this CTA's weight slices into SMEM (once) ----
    for (int i = tid; i < CPT * Hx; i += NTHR) {
        int cp = i >> 9, k = i & 511;
        int row = nb + cp;
        sw[WHZ0 + i] = Whz[((size_t)(0 * Hx + row)) * Hx + k];
        sw[WHR0 + i] = Whr[((size_t)(0 * Hx + row)) * Hx + k];
        sw[WHG0 + i] = Whg[((size_t)(0 * Hx + row)) * Hx + k];
        sw[WHZ1 + i] = Whz[((size_t)(1 * Hx + row)) * Hx + k];
        sw[WHR1 + i] = Whr[((size_t)(1 * Hx + row)) * Hx + k];
        sw[WHG1 + i] = Whg[((size_t)(1 * Hx + row)) * Hx + k];
        sw[WHZ2 + i] = Whz[((size_t)(2 * Hx + row)) * Hx + k];
        sw[WHR2 + i] = Whr[((size_t)(2 * Hx + row)) * Hx + k];
        sw[WHG2 + i] = Whg[((size_t)(2 * Hx + row)) * Hx + k];
        sw[WXZ1 + i] = Wxz[((size_t)(0 * Hx + row)) * Hx + k];
        sw[WXR1 + i] = Wxr[((size_t)(0 * Hx + row)) * Hx + k];
        sw[WXG1 + i] = Wxg[((size_t)(0 * Hx + row)) * Hx + k];
        sw[WXZ2 + i] = Wxz[((size_t)(1 * Hx + row)) * Hx + k];
        sw[WXR2 + i] = Wxr[((size_t)(1 * Hx + row)) * Hx + k];
        sw[WXG2 + i] = Wxg[((size_t)(1 * Hx + row)) * Hx + k];
    }
    for (int i = tid; i < CPT * Ix; i += NTHR) {
        int cp = i >> 7, j = i & 127;
        int row = nb + cp;
        sw[WX0Z + i] = Wx0z[(size_t)row * Ix + j];
        sw[WX0R + i] = Wx0r[(size_t)row * Ix + j];
        sw[WX0G + i] = Wx0g[(size_t)row * Ix + j];
    }
    for (int i = tid; i < Hx; i += NTHR)
        sw[WYOF + i] = Wy[(size_t)cta * Hx + i];
    if (tid < 12) {
        int l = tid >> 2, cp = tid & 3;
        sw[SM_BZ + tid] = bz[l * Hx + nb + cp];
        sw[SM_BR + tid] = br[l * Hx + nb + cp];
        sw[SM_BG + tid] = bg[l * Hx + nb + cp];
    }
    if (tid == 0) sw[SM_BY] = by[cta];
    __syncthreads();

    const int b = tid & 63;
    const int q = tid >> 6;

    const ulonglong2* h0u = (const ulonglong2*)(g_h);
    const ulonglong2* h1u = (const ulonglong2*)(g_h + 1 * HQ * Bx);
    const ulonglong2* h2u = (const ulonglong2*)(g_h + 2 * HQ * Bx);

    float z_reg = 0.f, xg_reg = 0.f;
    unsigned bv = 0;

    for (int t = 0; t < Sx; t++) {
        const ulonglong2* xt = (const ulonglong2*)(g_x0t + (size_t)t * IQ * Bx);

        // P(0,1): layer-0 z/r/xg + y for step t-1
        p1_partials<4, 32>(sw, b, q, h0u, xt, WHZ0, WHR0, WX0Z, WX0R, WX0G);
        if (t > 0) y_partial(sw, b, q);
        __syncthreads();
        p1_final(sw, b, q, cta, 0, (const float*)g_h, z_reg, xg_reg);
        if (t > 0 && q == 0) y_final(sw, b, cta, out, t - 1);
        bv++; gbar(bv * NCTA);

        // P(0,2)
        p2_partials(sw, b, q, WHG0);
        __syncthreads();
        p2_final(sw, b, q, cta, 0, z_reg, xg_reg);
        bv++; gbar(bv * NCTA);

        // P(1,1): x = new h0
        p1_partials<16, 128>(sw, b, q, h1u, h0u, WHZ1, WHR1, WXZ1, WXR1, WXG1);
        __syncthreads();
        p1_final(sw, b, q, cta, 1, (const float*)(g_h + HQ * Bx), z_reg, xg_reg);
        bv++; gbar(bv * NCTA);

        // P(1,2)
        p2_partials(sw, b, q, WHG1);
        __syncthreads();
        p2_final(sw, b, q, cta, 1, z_reg, xg_reg);
        bv++; gbar(bv * NCTA);

        // P(2,1): x = new h1
        p1_partials<16, 128>(sw, b, q, h2u, h1u, WHZ2, WHR2, WXZ2, WXR2, WXG2);
        __syncthreads();
        p1_final(sw, b, q, cta, 2, (const float*)(g_h + 2 * HQ * Bx), z_reg, xg_reg);
        bv++; gbar(bv * NCTA);

        // P(2,2)
        p2_partials(sw, b, q, WHG2);
        __syncthreads();
        p2_final(sw, b, q, cta, 2, z_reg, xg_reg);
        bv++; gbar(bv * NCTA);
    }

    // y for the final timestep
    y_partial(sw, b, q);
    __syncthreads();
    if (q == 0) y_final(sw, b, cta, out, Sx - 1);

    // hidden_out (B, L, H): each finalizer thread wrote its own column
    if (q < 4) {
        const int c = q;
#pragma unroll
        for (int l = 0; l < Lx; l++) {
            float hv = ((const float*)g_h)[(((size_t)l * HQ + cta) * Bx + b) * 4 + c];
            out[(size_t)Bx * Sx * Ox + ((size_t)b * Lx + l) * Hx + nb + c] = hv;
        }
    }
}

// ---------------------------------------------------------------------------
extern "C" void kernel_launch(void* const* d_in, const int* in_sizes, int n_in,
                              void* d_out, int out_size)
{
    const float* input = (const float*)d_in[0];
    const float* hs    = (const float*)d_in[1];
    const float* Wx0z  = (const float*)d_in[2];
    const float* Wx0r  = (const float*)d_in[3];
    const float* Wx0g  = (const float*)d_in[4];
    const float* Wxz   = (const float*)d_in[5];
    const float* Wxr   = (const float*)d_in[6];
    const float* Wxg   = (const float*)d_in[7];
    const float* Whz   = (const float*)d_in[8];
    const float* Whr   = (const float*)d_in[9];
    const float* Whg   = (const float*)d_in[10];
    const float* bz    = (const float*)d_in[11];
    const float* br    = (const float*)d_in[12];
    const float* bg    = (const float*)d_in[13];
    const float* Wy    = (const float*)d_in[14];
    const float* by    = (const float*)d_in[15];
    float* out = (float*)d_out;

    cudaFuncSetAttribute(gru_main, cudaFuncAttributeMaxDynamicSharedMemorySize, SMEM_BYTES);

    init_kernel<<<1024, 256>>>(input, hs);
    gru_main<<<NCTA, NTHR, SMEM_BYTES>>>(Wx0z, Wx0r, Wx0g, Wxz, Wxr, Wxg,
                                         Whz, Whr, Whg, bz, br, bg, Wy, by, out);
}

// round 13
// speedup vs baseline: 2.8744x; 1.2372x over previous
#include <cuda_runtime.h>
#include <math.h>
#include <stdint.h>

// ---------------------------------------------------------------------------
// MultilayerGRU  B=64 S=1024 I=128 H=512 L=3 O=128
// Persistent cooperative kernel, 128 CTAs x 512 threads.
// Thread (q=tid>>5, lane=tid&31) handles b={lane,lane+32} (R=2 batch blocking)
// and k-slice q (1/16 of K) for ALL 4 of this CTA's output columns.
// Packed fp32x2 FMAs; 16-way SMEM reduction; 6 grid barriers per timestep.
// ---------------------------------------------------------------------------

#define NCTA 128
#define NTHR 512
#define Bx   64
#define Sx   1024
#define Ix   128
#define Hx   512
#define Lx   3
#define Ox   128
#define CPT  4
#define HQ   (Hx/4)     // 128 float4 per activation row
#define IQ   (Ix/4)     // 32

// ---- shared memory layout (float offsets) ----
#define WHZ0 0
#define WHR0 2048
#define WHG0 4096
#define WX0Z 6144
#define WX0R 6656
#define WX0G 7168
#define WXZ1 7680
#define WXR1 9728
#define WXG1 11776
#define WHZ1 13824
#define WHR1 15872
#define WHG1 17920
#define WXZ2 19968
#define WXR2 22016
#define WXG2 24064
#define WHZ2 26112
#define WHR2 28160
#define WHG2 30208
#define WYOF 32256
#define SM_RED 32768            // 16 q * 16 slots * 64 b = 16384 floats
#define SM_BZ  49152
#define SM_BR  49168
#define SM_BG  49184
#define SM_BY  49200
#define SMEM_FLOATS 49216
#define SMEM_BYTES  (SMEM_FLOATS * 4)

// ---- global scratch ----
__device__ float4 g_x0t[(size_t)Sx * IQ * Bx];   // [s][j4][b]
__device__ float4 g_h[Lx * HQ * Bx];             // [l][k4][b]
__device__ float4 g_rh[HQ * Bx];                 // [k4][b]
__device__ unsigned g_bar;

// ---------------------------------------------------------------------------
__device__ __forceinline__ unsigned long long pfma(unsigned long long a,
                                                   unsigned long long b,
                                                   unsigned long long c) {
    unsigned long long d;
    asm("fma.rn.f32x2 %0, %1, %2, %3;" : "=l"(d) : "l"(a), "l"(b), "l"(c));
    return d;
}

__device__ __forceinline__ float phsum(unsigned long long v) {
    float lo = __uint_as_float((unsigned)(v & 0xffffffffULL));
    float hi = __uint_as_float((unsigned)(v >> 32));
    return lo + hi;
}

__device__ __forceinline__ float fsigm(float x) {
    return __fdividef(1.f, 1.f + __expf(-x));
}
__device__ __forceinline__ float ftanh(float x) {
    float e = __expf(-2.f * x);
    return __fdividef(1.f - e, 1.f + e);
}

__device__ __forceinline__ void gbar(unsigned target) {
    __syncthreads();
    if (threadIdx.x == 0) {
        unsigned* p = &g_bar;
        asm volatile("red.release.gpu.global.add.u32 [%0], 1;" :: "l"(p) : "memory");
        unsigned v;
        do {
            asm volatile("ld.acquire.gpu.global.u32 %0, [%1];" : "=r"(v) : "l"(p) : "memory");
        } while (v < target);
    }
    __syncthreads();
}

// ---------------------------------------------------------------------------
// Phase-1 partials: z/r over h, z/r/g over x, for all 4 columns, k-slice q,
// both batch halves b0 and b0+32.
template<int XKPT, int XSTR>
__device__ __forceinline__ void p1_partials(
    float* sw, int b0, int q,
    const ulonglong2* __restrict__ hsrc,
    const ulonglong2* __restrict__ xsrc,
    int whz, int whr, int wxz, int wxr, int wxg)
{
    const ulonglong2* wz2 = (const ulonglong2*)(sw + whz);
    const ulonglong2* wr2 = (const ulonglong2*)(sw + whr);
    const ulonglong2* xz2 = (const ulonglong2*)(sw + wxz);
    const ulonglong2* xr2 = (const ulonglong2*)(sw + wxr);
    const ulonglong2* xg2 = (const ulonglong2*)(sw + wxg);

    unsigned long long az[2][4], ar[2][4], ag[2][4];
#pragma unroll
    for (int r = 0; r < 2; r++)
#pragma unroll
        for (int cp = 0; cp < 4; cp++) { az[r][cp] = 0ULL; ar[r][cp] = 0ULL; ag[r][cp] = 0ULL; }

    const int k0 = q * 8;
#pragma unroll
    for (int k4 = k0; k4 < k0 + 8; k4++) {
        ulonglong2 h0 = hsrc[k4 * Bx + b0];
        ulonglong2 h1 = hsrc[k4 * Bx + b0 + 32];
#pragma unroll
        for (int cp = 0; cp < 4; cp++) {
            ulonglong2 w1 = wz2[cp * 128 + k4];
            ulonglong2 w2 = wr2[cp * 128 + k4];
            az[0][cp] = pfma(h0.x, w1.x, az[0][cp]);
            az[1][cp] = pfma(h1.x, w1.x, az[1][cp]);
            ar[0][cp] = pfma(h0.x, w2.x, ar[0][cp]);
            ar[1][cp] = pfma(h1.x, w2.x, ar[1][cp]);
            az[0][cp] = pfma(h0.y, w1.y, az[0][cp]);
            az[1][cp] = pfma(h1.y, w1.y, az[1][cp]);
            ar[0][cp] = pfma(h0.y, w2.y, ar[0][cp]);
            ar[1][cp] = pfma(h1.y, w2.y, ar[1][cp]);
        }
    }

    const int j0 = q * XKPT;
#pragma unroll
    for (int j4 = j0; j4 < j0 + XKPT; j4++) {
        ulonglong2 x0 = xsrc[j4 * Bx + b0];
        ulonglong2 x1 = xsrc[j4 * Bx + b0 + 32];
#pragma unroll
        for (int cp = 0; cp < 4; cp++) {
            ulonglong2 w1 = xz2[cp * XSTR + j4];
            ulonglong2 w2 = xr2[cp * XSTR + j4];
            ulonglong2 w3 = xg2[cp * XSTR + j4];
            az[0][cp] = pfma(x0.x, w1.x, az[0][cp]);
            az[1][cp] = pfma(x1.x, w1.x, az[1][cp]);
            ar[0][cp] = pfma(x0.x, w2.x, ar[0][cp]);
            ar[1][cp] = pfma(x1.x, w2.x, ar[1][cp]);
            ag[0][cp] = pfma(x0.x, w3.x, ag[0][cp]);
            ag[1][cp] = pfma(x1.x, w3.x, ag[1][cp]);
            az[0][cp] = pfma(x0.y, w1.y, az[0][cp]);
            az[1][cp] = pfma(x1.y, w1.y, az[1][cp]);
            ar[0][cp] = pfma(x0.y, w2.y, ar[0][cp]);
            ar[1][cp] = pfma(x1.y, w2.y, ar[1][cp]);
            ag[0][cp] = pfma(x0.y, w3.y, ag[0][cp]);
            ag[1][cp] = pfma(x1.y, w3.y, ag[1][cp]);
        }
    }

#pragma unroll
    for (int r = 0; r < 2; r++) {
        int b = b0 + 32 * r;
#pragma unroll
        for (int cp = 0; cp < 4; cp++) {
            sw[SM_RED + (q * 16 + cp)     * Bx + b] = phsum(az[r][cp]);
            sw[SM_RED + (q * 16 + 4 + cp) * Bx + b] = phsum(ar[r][cp]);
            sw[SM_RED + (q * 16 + 8 + cp) * Bx + b] = phsum(ag[r][cp]);
        }
    }
}

// Phase-1 finalize (after __syncthreads): warps q<4 own column c=q, 2 b's each.
__device__ __forceinline__ void p1_final(
    float* sw, int lane, int q, int cta, int l,
    const float* __restrict__ hbase,
    float2& z_reg, float2& xg_reg)
{
    if (q >= 4) return;
    const int c = q;
    float zz[2], xx[2];
#pragma unroll
    for (int r = 0; r < 2; r++) {
        const int b = lane + 32 * r;
        float sz = 0.f, sr = 0.f, sg = 0.f;
#pragma unroll
        for (int qq = 0; qq < 16; qq++) {
            sz += sw[SM_RED + (qq * 16 + c)     * Bx + b];
            sr += sw[SM_RED + (qq * 16 + 4 + c) * Bx + b];
            sg += sw[SM_RED + (qq * 16 + 8 + c) * Bx + b];
        }
        float z  = fsigm(sz + sw[SM_BZ + l * 4 + c]);
        float rr = fsigm(sr + sw[SM_BR + l * 4 + c]);
        zz[r] = z;
        xx[r] = sg + sw[SM_BG + l * 4 + c];
        float hcur = hbase[(cta * Bx + b) * 4 + c];
        ((float*)g_rh)[(cta * Bx + b) * 4 + c] = rr * hcur;
    }
    z_reg  = make_float2(zz[0], zz[1]);
    xg_reg = make_float2(xx[0], xx[1]);
}

// Phase-2 partials: g-dot over rh for all 4 columns, k-slice q, both b halves.
__device__ __forceinline__ void p2_partials(float* sw, int b0, int q, int whg)
{
    const ulonglong2* wg2 = (const ulonglong2*)(sw + whg);
    const ulonglong2* rh2 = (const ulonglong2*)g_rh;
    unsigned long long a[2][4];
#pragma unroll
    for (int r = 0; r < 2; r++)
#pragma unroll
        for (int cp = 0; cp < 4; cp++) a[r][cp] = 0ULL;
    const int k0 = q * 8;
#pragma unroll
    for (int k4 = k0; k4 < k0 + 8; k4++) {
        ulonglong2 r0 = rh2[k4 * Bx + b0];
        ulonglong2 r1 = rh2[k4 * Bx + b0 + 32];
#pragma unroll
        for (int cp = 0; cp < 4; cp++) {
            ulonglong2 w = wg2[cp * 128 + k4];
            a[0][cp] = pfma(r0.x, w.x, a[0][cp]);
            a[1][cp] = pfma(r1.x, w.x, a[1][cp]);
            a[0][cp] = pfma(r0.y, w.y, a[0][cp]);
            a[1][cp] = pfma(r1.y, w.y, a[1][cp]);
        }
    }
#pragma unroll
    for (int r = 0; r < 2; r++) {
        int b = b0 + 32 * r;
#pragma unroll
        for (int cp = 0; cp < 4; cp++)
            sw[SM_RED + (q * 16 + cp) * Bx + b] = phsum(a[r][cp]);
    }
}

__device__ __forceinline__ void p2_final(
    float* sw, int lane, int q, int cta, int l, float2 z_reg, float2 xg_reg)
{
    if (q >= 4) return;
    const int c = q;
#pragma unroll
    for (int r = 0; r < 2; r++) {
        const int b = lane + 32 * r;
        float s = 0.f;
#pragma unroll
        for (int qq = 0; qq < 16; qq++)
            s += sw[SM_RED + (qq * 16 + c) * Bx + b];
        float xg = (r == 0) ? xg_reg.x : xg_reg.y;
        float z  = (r == 0) ? z_reg.x  : z_reg.y;
        float g = ftanh(s + xg);
        float* hp = ((float*)g_h) + (((size_t)l * HQ + cta) * Bx + b) * 4 + c;
        float hold = *hp;
        *hp = fmaf(z, hold - g, g);
    }
}

// Output-projection partial over h2 (folded into P01 of step t+1).
__device__ __forceinline__ void y_partial(float* sw, int b0, int q)
{
    const ulonglong2* h2  = (const ulonglong2*)(g_h + 2 * HQ * Bx);
    const ulonglong2* wy2 = (const ulonglong2*)(sw + WYOF);
    unsigned long long a0 = 0ULL, a1 = 0ULL;
    const int k0 = q * 8;
#pragma unroll
    for (int k4 = k0; k4 < k0 + 8; k4++) {
        ulonglong2 w  = wy2[k4];
        ulonglong2 h0 = h2[k4 * Bx + b0];
        ulonglong2 h1 = h2[k4 * Bx + b0 + 32];
        a0 = pfma(h0.x, w.x, a0);
        a1 = pfma(h1.x, w.x, a1);
        a0 = pfma(h0.y, w.y, a0);
        a1 = pfma(h1.y, w.y, a1);
    }
    sw[SM_RED + (q * 16 + 12) * Bx + b0]      = phsum(a0);
    sw[SM_RED + (q * 16 + 12) * Bx + b0 + 32] = phsum(a1);
}

__device__ __forceinline__ void y_final(float* sw, int lane, int cta,
                                        float* __restrict__ out, int tdst)
{
#pragma unroll
    for (int r = 0; r < 2; r++) {
        const int b = lane + 32 * r;
        float s = 0.f;
#pragma unroll
        for (int qq = 0; qq < 16; qq++)
            s += sw[SM_RED + (qq * 16 + 12) * Bx + b];
        out[((size_t)b * Sx + tdst) * Ox + cta] = s + sw[SM_BY];
    }
}

// ---------------------------------------------------------------------------
__global__ void init_kernel(const float* __restrict__ in, const float* __restrict__ hs)
{
    size_t i = (size_t)blockIdx.x * blockDim.x + threadIdx.x;
    size_t stride = (size_t)gridDim.x * blockDim.x;
    if (i == 0) g_bar = 0;

    for (size_t idx = i; idx < (size_t)Bx * Lx * Hx; idx += stride) {
        int b = (int)(idx / (Lx * Hx));
        int l = (int)((idx / Hx) % Lx);
        int k = (int)(idx % Hx);
        ((float*)g_h)[(((size_t)l * HQ + (k >> 2)) * Bx + b) * 4 + (k & 3)] = hs[idx];
    }
    for (size_t idx = i; idx < (size_t)Bx * Sx * Ix; idx += stride) {
        int b = (int)(idx / ((size_t)Sx * Ix));
        int s = (int)((idx / Ix) % Sx);
        int j = (int)(idx % Ix);
        ((float*)g_x0t)[(((size_t)s * IQ + (j >> 2)) * Bx + b) * 4 + (j & 3)] = in[idx];
    }
}

__global__ void __launch_bounds__(NTHR, 1) gru_main(
    const float* __restrict__ Wx0z, const float* __restrict__ Wx0r, const float* __restrict__ Wx0g,
    const float* __restrict__ Wxz,  const float* __restrict__ Wxr,  const float* __restrict__ Wxg,
    const float* __restrict__ Whz,  const float* __restrict__ Whr,  const float* __restrict__ Whg,
    const float* __restrict__ bz,   const float* __restrict__ br,   const float* __restrict__ bg,
    const float* __restrict__ Wy,   const float* __restrict__ by,
    float* __restrict__ out)
{
    extern __shared__ float sw[];
    const int tid = threadIdx.x;
    const int cta = blockIdx.x;
    const int nb  = cta * CPT;

    // ---- load this CTA's weight slices into SMEM (once) ----
    for (int i = tid; i < CPT * Hx; i += NTHR) {
        int cp = i >> 9, k = i & 511;
        int row = nb + cp;
        sw[WHZ0 + i] = Whz[((size_t)(0 * Hx + row)) * Hx + k];
        sw[WHR0 + i] = Whr[((size_t)(0 * Hx + row)) * Hx + k];
        sw[WHG0 + i] = Whg[((size_t)(0 * Hx + row)) * Hx + k];
        sw[WHZ1 + i] = Whz[((size_t)(1 * Hx + row)) * Hx + k];
        sw[WHR1 + i] = Whr[((size_t)(1 * Hx + row)) * Hx + k];
        sw[WHG1 + i] = Whg[((size_t)(1 * Hx + row)) * Hx + k];
        sw[WHZ2 + i] = Whz[((size_t)(2 * Hx + row)) * Hx + k];
        sw[WHR2 + i] = Whr[((size_t)(2 * Hx + row)) * Hx + k];
        sw[WHG2 + i] = Whg[((size_t)(2 * Hx + row)) * Hx + k];
        sw[WXZ1 + i] = Wxz[((size_t)(0 * Hx + row)) * Hx + k];
        sw[WXR1 + i] = Wxr[((size_t)(0 * Hx + row)) * Hx + k];
        sw[WXG1 + i] = Wxg[((size_t)(0 * Hx + row)) * Hx + k];
        sw[WXZ2 + i] = Wxz[((size_t)(1 * Hx + row)) * Hx + k];
        sw[WXR2 + i] = Wxr[((size_t)(1 * Hx + row)) * Hx + k];
        sw[WXG2 + i] = Wxg[((size_t)(1 * Hx + row)) * Hx + k];
    }
    for (int i = tid; i < CPT * Ix; i += NTHR) {
        int cp = i >> 7, j = i & 127;
        int row = nb + cp;
        sw[WX0Z + i] = Wx0z[(size_t)row * Ix + j];
        sw[WX0R + i] = Wx0r[(size_t)row * Ix + j];
        sw[WX0G + i] = Wx0g[(size_t)row * Ix + j];
    }
    for (int i = tid; i < Hx; i += NTHR)
        sw[WYOF + i] = Wy[(size_t)cta * Hx + i];
    if (tid < 12) {
        int l = tid >> 2, cp = tid & 3;
        sw[SM_BZ + tid] = bz[l * Hx + nb + cp];
        sw[SM_BR + tid] = br[l * Hx + nb + cp];
        sw[SM_BG + tid] = bg[l * Hx + nb + cp];
    }
    if (tid == 0) sw[SM_BY] = by[cta];
    __syncthreads();

    const int lane = tid & 31;
    const int q    = tid >> 5;     // 16 k-slices

    const ulonglong2* h0u = (const ulonglong2*)(g_h);
    const ulonglong2* h1u = (const ulonglong2*)(g_h + 1 * HQ * Bx);
    const ulonglong2* h2u = (const ulonglong2*)(g_h + 2 * HQ * Bx);

    float2 z_reg = make_float2(0.f, 0.f), xg_reg = make_float2(0.f, 0.f);
    unsigned bv = 0;

    for (int t = 0; t < Sx; t++) {
        const ulonglong2* xt = (const ulonglong2*)(g_x0t + (size_t)t * IQ * Bx);

        // P(0,1): layer-0 z/r/xg + y for step t-1 (h2 still holds step t-1)
        p1_partials<2, 32>(sw, lane, q, h0u, xt, WHZ0, WHR0, WX0Z, WX0R, WX0G);
        if (t > 0) y_partial(sw, lane, q);
        __syncthreads();
        p1_final(sw, lane, q, cta, 0, (const float*)g_h, z_reg, xg_reg);
        if (t > 0 && q == 4) y_final(sw, lane, cta, out, t - 1);
        bv++; gbar(bv * NCTA);

        // P(0,2)
        p2_partials(sw, lane, q, WHG0);
        __syncthreads();
        p2_final(sw, lane, q, cta, 0, z_reg, xg_reg);
        bv++; gbar(bv * NCTA);

        // P(1,1): x = new h0
        p1_partials<8, 128>(sw, lane, q, h1u, h0u, WHZ1, WHR1, WXZ1, WXR1, WXG1);
        __syncthreads();
        p1_final(sw, lane, q, cta, 1, (const float*)(g_h + HQ * Bx), z_reg, xg_reg);
        bv++; gbar(bv * NCTA);

        // P(1,2)
        p2_partials(sw, lane, q, WHG1);
        __syncthreads();
        p2_final(sw, lane, q, cta, 1, z_reg, xg_reg);
        bv++; gbar(bv * NCTA);

        // P(2,1): x = new h1
        p1_partials<8, 128>(sw, lane, q, h2u, h1u, WHZ2, WHR2, WXZ2, WXR2, WXG2);
        __syncthreads();
        p1_final(sw, lane, q, cta, 2, (const float*)(g_h + 2 * HQ * Bx), z_reg, xg_reg);
        bv++; gbar(bv * NCTA);

        // P(2,2)
        p2_partials(sw, lane, q, WHG2);
        __syncthreads();
        p2_final(sw, lane, q, cta, 2, z_reg, xg_reg);
        bv++; gbar(bv * NCTA);
    }

    // y for the final timestep
    y_partial(sw, lane, q);
    __syncthreads();
    if (q == 4) y_final(sw, lane, cta, out, Sx - 1);

    // hidden_out (B, L, H)
    if (q < 4) {
        const int c = q;
#pragma unroll
        for (int r = 0; r < 2; r++) {
            const int b = lane + 32 * r;
#pragma unroll
            for (int l = 0; l < Lx; l++) {
                float hv = ((const float*)g_h)[(((size_t)l * HQ + cta) * Bx + b) * 4 + c];
                out[(size_t)Bx * Sx * Ox + ((size_t)b * Lx + l) * Hx + nb + c] = hv;
            }
        }
    }
}

// ---------------------------------------------------------------------------
extern "C" void kernel_launch(void* const* d_in, const int* in_sizes, int n_in,
                              void* d_out, int out_size)
{
    const float* input = (const float*)d_in[0];
    const float* hs    = (const float*)d_in[1];
    const float* Wx0z  = (const float*)d_in[2];
    const float* Wx0r  = (const float*)d_in[3];
    const float* Wx0g  = (const float*)d_in[4];
    const float* Wxz   = (const float*)d_in[5];
    const float* Wxr   = (const float*)d_in[6];
    const float* Wxg   = (const float*)d_in[7];
    const float* Whz   = (const float*)d_in[8];
    const float* Whr   = (const float*)d_in[9];
    const float* Whg   = (const float*)d_in[10];
    const float* bz    = (const float*)d_in[11];
    const float* br    = (const float*)d_in[12];
    const float* bg    = (const float*)d_in[13];
    const float* Wy    = (const float*)d_in[14];
    const float* by    = (const float*)d_in[15];
    float* out = (float*)d_out;

    cudaFuncSetAttribute(gru_main, cudaFuncAttributeMaxDynamicSharedMemorySize, SMEM_BYTES);

    init_kernel<<<1024, 256>>>(input, hs);
    gru_main<<<NCTA, NTHR, SMEM_BYTES>>>(Wx0z, Wx0r, Wx0g, Wxz, Wxr, Wxg,
                                         Whz, Whr, Whg, bz, br, bg, Wy, by, out);
}